// round 4
// baseline (speedup 1.0000x reference)
#include <cuda_runtime.h>

// DenselyCnnAttLayer, persistent warp-per-row formulation.
// out[b,s,d] = sum_l softmax_m( sum_l' s[b,s,l'] * Ws[s,l',m] )[l] * x_l[b,s,d]
// B=64, S=512, L=6, D=512, fp32. Minimal traffic: 6 reads + 1 write = ~470MB.
//
// R4 vs R3 (ncu 66.5us, DRAM 84.7%, 13.8 waves of 8192 CTAs): persistent
// grid-stride. grid = 152 SMs x 4 CTAs; each warp loops over rows. Removes
// wave-transition overhead + last-wave tail, keeps the LDG stream continuous.
// Per-row work unchanged: 24 front-batched LDG.128, shuffle-only reduction,
// redundant per-lane 6x6 softmax, 4 streaming STG.128.

#define DD    512
#define LL    6
#define CHNK  4            // float4 chunks per lane per layer (512/32/4)
#define NTHR  128          // 4 warps per CTA
#define NSM   152          // GB300 SM count
#define CPSM  4            // resident CTAs per SM (128 regs/thread)

__global__ __launch_bounds__(NTHR, CPSM)
void dense_att_kernel(const float* __restrict__ x0,
                      const float* __restrict__ x1,
                      const float* __restrict__ x2,
                      const float* __restrict__ x3,
                      const float* __restrict__ x4,
                      const float* __restrict__ x5,
                      const float* __restrict__ Ws,   // [S, L, L]
                      float* __restrict__ out,        // [B, S, D]
                      int rows)
{
    const int warp  = threadIdx.x >> 5;
    const int lane  = threadIdx.x & 31;
    const int wglob = blockIdx.x * (NTHR / 32) + warp;
    const int wtot  = gridDim.x * (NTHR / 32);

    const float* xs[LL] = {x0, x1, x2, x3, x4, x5};

    for (int row = wglob; row < rows; row += wtot) {
        const int s = row & 511;                       // S = 512
        const size_t base = (size_t)row * DD + (size_t)lane * 4;

        float4 v[LL][CHNK];
#pragma unroll
        for (int j = 0; j < LL; j++) {
#pragma unroll
            for (int c = 0; c < CHNK; c++) {
                v[j][c] = __ldcs(reinterpret_cast<const float4*>(xs[j] + base + c * 128));
            }
        }

        float p[LL];
#pragma unroll
        for (int j = 0; j < LL; j++) {
            float a0 = (v[j][0].x + v[j][0].y) + (v[j][0].z + v[j][0].w);
            float a1 = (v[j][1].x + v[j][1].y) + (v[j][1].z + v[j][1].w);
            float a2 = (v[j][2].x + v[j][2].y) + (v[j][2].z + v[j][2].w);
            float a3 = (v[j][3].x + v[j][3].y) + (v[j][3].z + v[j][3].w);
            p[j] = (a0 + a1) + (a2 + a3);
        }

        // Warp butterfly: all lanes end with the full per-layer sums.
#pragma unroll
        for (int off = 16; off > 0; off >>= 1) {
#pragma unroll
            for (int j = 0; j < LL; j++) {
                p[j] += __shfl_xor_sync(0xffffffffu, p[j], off);
            }
        }

        // Redundant per-lane 6x6 projection + softmax (warp-uniform Ws loads).
        const float* W = Ws + (size_t)s * (LL * LL);
        float logit[LL];
#pragma unroll
        for (int m = 0; m < LL; m++) logit[m] = 0.0f;
#pragma unroll
        for (int l = 0; l < LL; l++) {
            const float sl = p[l];
#pragma unroll
            for (int m = 0; m < LL; m++) {
                logit[m] = fmaf(sl, __ldg(W + l * LL + m), logit[m]);
            }
        }

        float mx = logit[0];
#pragma unroll
        for (int m = 1; m < LL; m++) mx = fmaxf(mx, logit[m]);
        float a[LL];
        float den = 0.0f;
#pragma unroll
        for (int m = 0; m < LL; m++) {
            a[m] = __expf(logit[m] - mx);
            den += a[m];
        }
        const float inv = __frcp_rn(den);
#pragma unroll
        for (int m = 0; m < LL; m++) a[m] *= inv;

        // Weighted combine over layers, 4 coalesced streaming stores.
#pragma unroll
        for (int c = 0; c < CHNK; c++) {
            float4 o;
            o.x = o.y = o.z = o.w = 0.0f;
#pragma unroll
            for (int j = 0; j < LL; j++) {
                o.x = fmaf(a[j], v[j][c].x, o.x);
                o.y = fmaf(a[j], v[j][c].y, o.y);
                o.z = fmaf(a[j], v[j][c].z, o.z);
                o.w = fmaf(a[j], v[j][c].w, o.w);
            }
            __stcs(reinterpret_cast<float4*>(out + base + c * 128), o);
        }
    }
}

extern "C" void kernel_launch(void* const* d_in, const int* in_sizes, int n_in,
                              void* d_out, int out_size)
{
    const float* x0 = (const float*)d_in[0];
    const float* x1 = (const float*)d_in[1];
    const float* x2 = (const float*)d_in[2];
    const float* x3 = (const float*)d_in[3];
    const float* x4 = (const float*)d_in[4];
    const float* x5 = (const float*)d_in[5];
    const float* Ws = (const float*)d_in[6];
    float* out = (float*)d_out;

    const int rows = in_sizes[0] / DD;          // B*S = 32768
    dense_att_kernel<<<NSM * CPSM, NTHR>>>(x0, x1, x2, x3, x4, x5, Ws, out, rows);
}